// round 5
// baseline (speedup 1.0000x reference)
#include <cuda_runtime.h>

// LIF scan, bit-faithful to the reference per-op rounding:
//   v_euler = v + ((-v + 3000*I) / 150) * 0.01   (each op RN-rounded; div via
//   Markstein 3-op refinement == div.rn.f32)
//   v = (v >= 15) ? 0 : v_euler ; v = (v >= 15) ? 30 : v
// Carried-predicate invariant: entering any step v is exactly 30 or < 15, so the
// reset predicate equals the previous step's spike predicate (one compare/step).
//
// R5 shape: float2 lanes, 1024 blocks x 64 thr (13.8 warps/SM — the measured
// sweet spot), UNROLL_T=20 double-buffered prefetch (~70 KB in flight/SM),
// streaming cache ops on both streams.

#define UNROLL_T 20
#define T_STEPS 1000
#define N_NEUR 131072
#define N2 (N_NEUR / 2)  // float2 pairs per timestep = 65536

__device__ __forceinline__ void lif_step(float& v, bool& p, float I) {
    const float y = (float)(1.0 / 150.0);        // RN(1/150)
    float pr  = __fmul_rn(I, 3000.0f);
    float num = __fadd_rn(pr, -v);
    float q0  = __fmul_rn(num, y);
    float rr  = __fmaf_rn(q0, -150.0f, num);     // exact remainder (FMA)
    float q   = __fmaf_rn(rr, y, q0);            // correctly rounded num/150
    float dv  = __fmul_rn(q, 0.01f);
    float ve  = __fadd_rn(v, dv);
    bool spike = (ve >= 15.0f) && (!p);
    float tv = p ? 0.0f : ve;
    v = spike ? 30.0f : tv;
    p = spike;
}

__global__ void __launch_bounds__(64)
lif_kernel_fixed(const float2* __restrict__ stim, float2* __restrict__ out) {
    const int idx = blockIdx.x * 64 + threadIdx.x;     // pair index 0..N2-1
    const float2* __restrict__ sp = stim + idx;
    float2* __restrict__ op = out + idx;

    float v0 = 0.0f, v1 = 0.0f;
    bool p0 = false, p1 = false;

    const size_t row   = (size_t)N2;                   // pairs per timestep
    const size_t chunk = (size_t)UNROLL_T * row;

    float2 buf[UNROLL_T];
    #pragma unroll
    for (int u = 0; u < UNROLL_T; u++) buf[u] = __ldcs(sp + (size_t)u * row);

    const float2* __restrict__ ld = sp + chunk;
    float2* __restrict__ st = op;

    const int nchunks = T_STEPS / UNROLL_T;            // 50

    for (int c = 0; c < nchunks - 1; c++) {
        float2 nbuf[UNROLL_T];
        // Prefetch next chunk: 20 independent LDG.64.STRM in flight
        #pragma unroll
        for (int u = 0; u < UNROLL_T; u++) nbuf[u] = __ldcs(ld + (size_t)u * row);
        // Compute + stream-store current chunk
        #pragma unroll
        for (int u = 0; u < UNROLL_T; u++) {
            lif_step(v0, p0, buf[u].x);
            lif_step(v1, p1, buf[u].y);
            __stcs(st + (size_t)u * row, make_float2(v0, v1));
        }
        #pragma unroll
        for (int u = 0; u < UNROLL_T; u++) buf[u] = nbuf[u];
        ld += chunk;
        st += chunk;
    }
    #pragma unroll
    for (int u = 0; u < UNROLL_T; u++) {
        lif_step(v0, p0, buf[u].x);
        lif_step(v1, p1, buf[u].y);
        __stcs(st + (size_t)u * row, make_float2(v0, v1));
    }
}

// Generic fallback (any N, T=1000 assumed) — correctness path for odd shapes.
__global__ void lif_kernel_generic(const float* __restrict__ stim,
                                   float* __restrict__ out, int N, int T) {
    int n = blockIdx.x * blockDim.x + threadIdx.x;
    if (n >= N) return;
    float v = 0.0f;
    bool p = false;
    for (int t = 0; t < T; t++) {
        lif_step(v, p, stim[(size_t)t * N + n]);
        out[(size_t)t * N + n] = v;
    }
}

extern "C" void kernel_launch(void* const* d_in, const int* in_sizes, int n_in,
                              void* d_out, int out_size) {
    const float* stim = (const float*)d_in[0];
    float* out = (float*)d_out;

    if (in_sizes[0] == T_STEPS * N_NEUR && out_size == T_STEPS * N_NEUR) {
        // 65536 pairs / 64 threads = 1024 blocks (one wave on 148 SMs)
        lif_kernel_fixed<<<N2 / 64, 64>>>((const float2*)stim, (float2*)out);
    } else {
        int T = 1000;
        int N = in_sizes[0] / T;
        int threads = 128;
        int blocks = (N + threads - 1) / threads;
        lif_kernel_generic<<<blocks, threads>>>(stim, out, N, T);
    }
}

// round 6
// speedup vs baseline: 1.0093x; 1.0093x over previous
#include <cuda_runtime.h>

// LIF scan, bit-faithful to the reference per-op rounding:
//   v_euler = v + ((-v + 3000*I) / 150) * 0.01   (each op RN-rounded; div via
//   Markstein 3-op refinement == div.rn.f32)
//   v = (v >= 15) ? 0 : v_euler ; v = (v >= 15) ? 30 : v
// Carried-predicate invariant: entering any step v is exactly 30 or < 15, so the
// reset predicate equals the previous step's spike predicate (one compare/step).
//
// R6 = R5 resubmitted VERBATIM: reproducibility test to resolve the bench(173.7us)
// vs ncu(156.9us) discrepancy before further tuning. float2 lanes, 1024x64,
// UNROLL_T=20 double-buffered prefetch, streaming cache ops.

#define UNROLL_T 20
#define T_STEPS 1000
#define N_NEUR 131072
#define N2 (N_NEUR / 2)  // float2 pairs per timestep = 65536

__device__ __forceinline__ void lif_step(float& v, bool& p, float I) {
    const float y = (float)(1.0 / 150.0);        // RN(1/150)
    float pr  = __fmul_rn(I, 3000.0f);
    float num = __fadd_rn(pr, -v);
    float q0  = __fmul_rn(num, y);
    float rr  = __fmaf_rn(q0, -150.0f, num);     // exact remainder (FMA)
    float q   = __fmaf_rn(rr, y, q0);            // correctly rounded num/150
    float dv  = __fmul_rn(q, 0.01f);
    float ve  = __fadd_rn(v, dv);
    bool spike = (ve >= 15.0f) && (!p);
    float tv = p ? 0.0f : ve;
    v = spike ? 30.0f : tv;
    p = spike;
}

__global__ void __launch_bounds__(64)
lif_kernel_fixed(const float2* __restrict__ stim, float2* __restrict__ out) {
    const int idx = blockIdx.x * 64 + threadIdx.x;     // pair index 0..N2-1
    const float2* __restrict__ sp = stim + idx;
    float2* __restrict__ op = out + idx;

    float v0 = 0.0f, v1 = 0.0f;
    bool p0 = false, p1 = false;

    const size_t row   = (size_t)N2;                   // pairs per timestep
    const size_t chunk = (size_t)UNROLL_T * row;

    float2 buf[UNROLL_T];
    #pragma unroll
    for (int u = 0; u < UNROLL_T; u++) buf[u] = __ldcs(sp + (size_t)u * row);

    const float2* __restrict__ ld = sp + chunk;
    float2* __restrict__ st = op;

    const int nchunks = T_STEPS / UNROLL_T;            // 50

    for (int c = 0; c < nchunks - 1; c++) {
        float2 nbuf[UNROLL_T];
        // Prefetch next chunk: 20 independent LDG.64.STRM in flight
        #pragma unroll
        for (int u = 0; u < UNROLL_T; u++) nbuf[u] = __ldcs(ld + (size_t)u * row);
        // Compute + stream-store current chunk
        #pragma unroll
        for (int u = 0; u < UNROLL_T; u++) {
            lif_step(v0, p0, buf[u].x);
            lif_step(v1, p1, buf[u].y);
            __stcs(st + (size_t)u * row, make_float2(v0, v1));
        }
        #pragma unroll
        for (int u = 0; u < UNROLL_T; u++) buf[u] = nbuf[u];
        ld += chunk;
        st += chunk;
    }
    #pragma unroll
    for (int u = 0; u < UNROLL_T; u++) {
        lif_step(v0, p0, buf[u].x);
        lif_step(v1, p1, buf[u].y);
        __stcs(st + (size_t)u * row, make_float2(v0, v1));
    }
}

// Generic fallback (any N, T=1000 assumed) — correctness path for odd shapes.
__global__ void lif_kernel_generic(const float* __restrict__ stim,
                                   float* __restrict__ out, int N, int T) {
    int n = blockIdx.x * blockDim.x + threadIdx.x;
    if (n >= N) return;
    float v = 0.0f;
    bool p = false;
    for (int t = 0; t < T; t++) {
        lif_step(v, p, stim[(size_t)t * N + n]);
        out[(size_t)t * N + n] = v;
    }
}

extern "C" void kernel_launch(void* const* d_in, const int* in_sizes, int n_in,
                              void* d_out, int out_size) {
    const float* stim = (const float*)d_in[0];
    float* out = (float*)d_out;

    if (in_sizes[0] == T_STEPS * N_NEUR && out_size == T_STEPS * N_NEUR) {
        // 65536 pairs / 64 threads = 1024 blocks (one wave on 148 SMs)
        lif_kernel_fixed<<<N2 / 64, 64>>>((const float2*)stim, (float2*)out);
    } else {
        int T = 1000;
        int N = in_sizes[0] / T;
        int threads = 128;
        int blocks = (N + threads - 1) / threads;
        lif_kernel_generic<<<blocks, threads>>>(stim, out, N, T);
    }
}

// round 7
// speedup vs baseline: 1.0469x; 1.0372x over previous
#include <cuda_runtime.h>

// LIF scan, bit-faithful to the reference per-op rounding:
//   v_euler = v + ((-v + 3000*I) / 150) * 0.01   (each op RN-rounded; div via
//   Markstein 3-op refinement == div.rn.f32)
//   v = (v >= 15) ? 0 : v_euler ; v = (v >= 15) ? 30 : v
// Carried-predicate invariant: entering any step v is exactly 30 or < 15, so the
// reset predicate equals the previous step's spike predicate (one compare/step).
//
// R7: probe the sustained-replay penalty curve at UNROLL_T=14 (between the
// U=10 champion, bench gap +2us, and U=20, single-shot-fastest but +17us gap
// under sustained replay). float2 lanes, 1024x64 (13.8 warps/SM), streaming ops.
// 1000 = 71*14 + 6 -> 71 full chunks + 6-step tail.

#define UNROLL_T 14
#define TAIL_T 6
#define T_STEPS 1000
#define N_NEUR 131072
#define N2 (N_NEUR / 2)  // float2 pairs per timestep = 65536

__device__ __forceinline__ void lif_step(float& v, bool& p, float I) {
    const float y = (float)(1.0 / 150.0);        // RN(1/150)
    float pr  = __fmul_rn(I, 3000.0f);
    float num = __fadd_rn(pr, -v);
    float q0  = __fmul_rn(num, y);
    float rr  = __fmaf_rn(q0, -150.0f, num);     // exact remainder (FMA)
    float q   = __fmaf_rn(rr, y, q0);            // correctly rounded num/150
    float dv  = __fmul_rn(q, 0.01f);
    float ve  = __fadd_rn(v, dv);
    bool spike = (ve >= 15.0f) && (!p);
    float tv = p ? 0.0f : ve;
    v = spike ? 30.0f : tv;
    p = spike;
}

__global__ void __launch_bounds__(64)
lif_kernel_fixed(const float2* __restrict__ stim, float2* __restrict__ out) {
    const int idx = blockIdx.x * 64 + threadIdx.x;     // pair index 0..N2-1
    const float2* __restrict__ sp = stim + idx;

    float v0 = 0.0f, v1 = 0.0f;
    bool p0 = false, p1 = false;

    const size_t row   = (size_t)N2;                   // pairs per timestep
    const size_t chunk = (size_t)UNROLL_T * row;

    float2 buf[UNROLL_T];
    #pragma unroll
    for (int u = 0; u < UNROLL_T; u++) buf[u] = __ldcs(sp + (size_t)u * row);

    const float2* __restrict__ ld = sp + chunk;
    float2* __restrict__ st = out + idx;

    // 71 full chunks total; 70 loop iterations each prefetch the next chunk.
    for (int c = 0; c < 70; c++) {
        float2 nbuf[UNROLL_T];
        #pragma unroll
        for (int u = 0; u < UNROLL_T; u++) nbuf[u] = __ldcs(ld + (size_t)u * row);
        #pragma unroll
        for (int u = 0; u < UNROLL_T; u++) {
            lif_step(v0, p0, buf[u].x);
            lif_step(v1, p1, buf[u].y);
            __stcs(st + (size_t)u * row, make_float2(v0, v1));
        }
        #pragma unroll
        for (int u = 0; u < UNROLL_T; u++) buf[u] = nbuf[u];
        ld += chunk;
        st += chunk;
    }

    // buf holds chunk 70 (steps 980..993); ld points at step 994. Prefetch tail.
    float2 tbuf[TAIL_T];
    #pragma unroll
    for (int u = 0; u < TAIL_T; u++) tbuf[u] = __ldcs(ld + (size_t)u * row);

    // Compute last full chunk
    #pragma unroll
    for (int u = 0; u < UNROLL_T; u++) {
        lif_step(v0, p0, buf[u].x);
        lif_step(v1, p1, buf[u].y);
        __stcs(st + (size_t)u * row, make_float2(v0, v1));
    }
    st += chunk;

    // Tail: steps 994..999
    #pragma unroll
    for (int u = 0; u < TAIL_T; u++) {
        lif_step(v0, p0, tbuf[u].x);
        lif_step(v1, p1, tbuf[u].y);
        __stcs(st + (size_t)u * row, make_float2(v0, v1));
    }
}

// Generic fallback (any N, T=1000 assumed) — correctness path for odd shapes.
__global__ void lif_kernel_generic(const float* __restrict__ stim,
                                   float* __restrict__ out, int N, int T) {
    int n = blockIdx.x * blockDim.x + threadIdx.x;
    if (n >= N) return;
    float v = 0.0f;
    bool p = false;
    for (int t = 0; t < T; t++) {
        lif_step(v, p, stim[(size_t)t * N + n]);
        out[(size_t)t * N + n] = v;
    }
}

extern "C" void kernel_launch(void* const* d_in, const int* in_sizes, int n_in,
                              void* d_out, int out_size) {
    const float* stim = (const float*)d_in[0];
    float* out = (float*)d_out;

    if (in_sizes[0] == T_STEPS * N_NEUR && out_size == T_STEPS * N_NEUR) {
        // 65536 pairs / 64 threads = 1024 blocks (one wave on 148 SMs)
        lif_kernel_fixed<<<N2 / 64, 64>>>((const float2*)stim, (float2*)out);
    } else {
        int T = 1000;
        int N = in_sizes[0] / T;
        int threads = 128;
        int blocks = (N + threads - 1) / threads;
        lif_kernel_generic<<<blocks, threads>>>(stim, out, N, T);
    }
}

// round 8
// speedup vs baseline: 1.0889x; 1.0401x over previous
#include <cuda_runtime.h>

// LIF scan, bit-faithful to the reference per-op rounding:
//   v_euler = v + ((-v + 3000*I) / 150) * 0.01   (each op RN-rounded; div via
//   Markstein 3-op refinement == div.rn.f32)
//   v = (v >= 15) ? 0 : v_euler ; v = (v >= 15) ? 30 : v
// Carried-predicate invariant: entering any step v is exactly 30 or < 15, so the
// reset predicate equals the previous step's spike predicate (one compare/step).
//
// R8: UNROLL_T=12 — interior probe of the sustained-replay U-curve
// (bench: U8=173.4, U10=164.3, U14=165.9, U20=172.1). float2 lanes,
// 1024x64 (13.8 warps/SM), double-buffered prefetch, streaming cache ops.
// 1000 = 83*12 + 4 -> 83 full chunks + 4-step tail.

#define UNROLL_T 12
#define TAIL_T 4
#define T_STEPS 1000
#define N_NEUR 131072
#define N2 (N_NEUR / 2)  // float2 pairs per timestep = 65536

__device__ __forceinline__ void lif_step(float& v, bool& p, float I) {
    const float y = (float)(1.0 / 150.0);        // RN(1/150)
    float pr  = __fmul_rn(I, 3000.0f);
    float num = __fadd_rn(pr, -v);
    float q0  = __fmul_rn(num, y);
    float rr  = __fmaf_rn(q0, -150.0f, num);     // exact remainder (FMA)
    float q   = __fmaf_rn(rr, y, q0);            // correctly rounded num/150
    float dv  = __fmul_rn(q, 0.01f);
    float ve  = __fadd_rn(v, dv);
    bool spike = (ve >= 15.0f) && (!p);
    float tv = p ? 0.0f : ve;
    v = spike ? 30.0f : tv;
    p = spike;
}

__global__ void __launch_bounds__(64)
lif_kernel_fixed(const float2* __restrict__ stim, float2* __restrict__ out) {
    const int idx = blockIdx.x * 64 + threadIdx.x;     // pair index 0..N2-1
    const float2* __restrict__ sp = stim + idx;

    float v0 = 0.0f, v1 = 0.0f;
    bool p0 = false, p1 = false;

    const size_t row   = (size_t)N2;                   // pairs per timestep
    const size_t chunk = (size_t)UNROLL_T * row;

    float2 buf[UNROLL_T];
    #pragma unroll
    for (int u = 0; u < UNROLL_T; u++) buf[u] = __ldcs(sp + (size_t)u * row);

    const float2* __restrict__ ld = sp + chunk;
    float2* __restrict__ st = out + idx;

    // 83 full chunks total; 82 loop iterations each prefetch the next chunk.
    for (int c = 0; c < 82; c++) {
        float2 nbuf[UNROLL_T];
        #pragma unroll
        for (int u = 0; u < UNROLL_T; u++) nbuf[u] = __ldcs(ld + (size_t)u * row);
        #pragma unroll
        for (int u = 0; u < UNROLL_T; u++) {
            lif_step(v0, p0, buf[u].x);
            lif_step(v1, p1, buf[u].y);
            __stcs(st + (size_t)u * row, make_float2(v0, v1));
        }
        #pragma unroll
        for (int u = 0; u < UNROLL_T; u++) buf[u] = nbuf[u];
        ld += chunk;
        st += chunk;
    }

    // buf holds chunk 82 (steps 984..995); ld points at step 996. Prefetch tail.
    float2 tbuf[TAIL_T];
    #pragma unroll
    for (int u = 0; u < TAIL_T; u++) tbuf[u] = __ldcs(ld + (size_t)u * row);

    // Compute last full chunk
    #pragma unroll
    for (int u = 0; u < UNROLL_T; u++) {
        lif_step(v0, p0, buf[u].x);
        lif_step(v1, p1, buf[u].y);
        __stcs(st + (size_t)u * row, make_float2(v0, v1));
    }
    st += chunk;

    // Tail: steps 996..999
    #pragma unroll
    for (int u = 0; u < TAIL_T; u++) {
        lif_step(v0, p0, tbuf[u].x);
        lif_step(v1, p1, tbuf[u].y);
        __stcs(st + (size_t)u * row, make_float2(v0, v1));
    }
}

// Generic fallback (any N, T=1000 assumed) — correctness path for odd shapes.
__global__ void lif_kernel_generic(const float* __restrict__ stim,
                                   float* __restrict__ out, int N, int T) {
    int n = blockIdx.x * blockDim.x + threadIdx.x;
    if (n >= N) return;
    float v = 0.0f;
    bool p = false;
    for (int t = 0; t < T; t++) {
        lif_step(v, p, stim[(size_t)t * N + n]);
        out[(size_t)t * N + n] = v;
    }
}

extern "C" void kernel_launch(void* const* d_in, const int* in_sizes, int n_in,
                              void* d_out, int out_size) {
    const float* stim = (const float*)d_in[0];
    float* out = (float*)d_out;

    if (in_sizes[0] == T_STEPS * N_NEUR && out_size == T_STEPS * N_NEUR) {
        // 65536 pairs / 64 threads = 1024 blocks (one wave on 148 SMs)
        lif_kernel_fixed<<<N2 / 64, 64>>>((const float2*)stim, (float2*)out);
    } else {
        int T = 1000;
        int N = in_sizes[0] / T;
        int threads = 128;
        int blocks = (N + threads - 1) / threads;
        lif_kernel_generic<<<blocks, threads>>>(stim, out, N, T);
    }
}

// round 9
// speedup vs baseline: 1.0895x; 1.0006x over previous
#include <cuda_runtime.h>

// LIF scan, bit-faithful to the reference per-op rounding:
//   v_euler = v + ((-v + 3000*I) / 150) * 0.01   (each op RN-rounded; div via
//   Markstein 3-op refinement == div.rn.f32)
//   v = (v >= 15) ? 0 : v_euler ; v = (v >= 15) ? 30 : v
// Carried-predicate invariant: entering any step v is exactly 30 or < 15, so the
// reset predicate equals the previous step's spike predicate (one compare/step).
//
// R9: UNROLL_T=13 — edge probe of the sustained-replay cliff found in (12,14].
// Bench curve: U8=173.4, U10=164.3, U12=159.5 (gap +2.8), U14=165.9 (gap +12.9),
// U20=172.1 (gap +17.5). float2 lanes, 1024x64 (13.8 warps/SM), double-buffered
// prefetch, streaming cache ops. 1000 = 76*13 + 12 -> 76 full chunks + 12 tail.

#define UNROLL_T 13
#define TAIL_T 12
#define T_STEPS 1000
#define N_NEUR 131072
#define N2 (N_NEUR / 2)  // float2 pairs per timestep = 65536

__device__ __forceinline__ void lif_step(float& v, bool& p, float I) {
    const float y = (float)(1.0 / 150.0);        // RN(1/150)
    float pr  = __fmul_rn(I, 3000.0f);
    float num = __fadd_rn(pr, -v);
    float q0  = __fmul_rn(num, y);
    float rr  = __fmaf_rn(q0, -150.0f, num);     // exact remainder (FMA)
    float q   = __fmaf_rn(rr, y, q0);            // correctly rounded num/150
    float dv  = __fmul_rn(q, 0.01f);
    float ve  = __fadd_rn(v, dv);
    bool spike = (ve >= 15.0f) && (!p);
    float tv = p ? 0.0f : ve;
    v = spike ? 30.0f : tv;
    p = spike;
}

__global__ void __launch_bounds__(64)
lif_kernel_fixed(const float2* __restrict__ stim, float2* __restrict__ out) {
    const int idx = blockIdx.x * 64 + threadIdx.x;     // pair index 0..N2-1
    const float2* __restrict__ sp = stim + idx;

    float v0 = 0.0f, v1 = 0.0f;
    bool p0 = false, p1 = false;

    const size_t row   = (size_t)N2;                   // pairs per timestep
    const size_t chunk = (size_t)UNROLL_T * row;

    float2 buf[UNROLL_T];
    #pragma unroll
    for (int u = 0; u < UNROLL_T; u++) buf[u] = __ldcs(sp + (size_t)u * row);

    const float2* __restrict__ ld = sp + chunk;
    float2* __restrict__ st = out + idx;

    // 76 full chunks total; 75 loop iterations each prefetch the next chunk.
    for (int c = 0; c < 75; c++) {
        float2 nbuf[UNROLL_T];
        #pragma unroll
        for (int u = 0; u < UNROLL_T; u++) nbuf[u] = __ldcs(ld + (size_t)u * row);
        #pragma unroll
        for (int u = 0; u < UNROLL_T; u++) {
            lif_step(v0, p0, buf[u].x);
            lif_step(v1, p1, buf[u].y);
            __stcs(st + (size_t)u * row, make_float2(v0, v1));
        }
        #pragma unroll
        for (int u = 0; u < UNROLL_T; u++) buf[u] = nbuf[u];
        ld += chunk;
        st += chunk;
    }

    // buf holds chunk 75 (steps 975..987); ld points at step 988. Prefetch tail.
    float2 tbuf[TAIL_T];
    #pragma unroll
    for (int u = 0; u < TAIL_T; u++) tbuf[u] = __ldcs(ld + (size_t)u * row);

    // Compute last full chunk
    #pragma unroll
    for (int u = 0; u < UNROLL_T; u++) {
        lif_step(v0, p0, buf[u].x);
        lif_step(v1, p1, buf[u].y);
        __stcs(st + (size_t)u * row, make_float2(v0, v1));
    }
    st += chunk;

    // Tail: steps 988..999
    #pragma unroll
    for (int u = 0; u < TAIL_T; u++) {
        lif_step(v0, p0, tbuf[u].x);
        lif_step(v1, p1, tbuf[u].y);
        __stcs(st + (size_t)u * row, make_float2(v0, v1));
    }
}

// Generic fallback (any N, T=1000 assumed) — correctness path for odd shapes.
__global__ void lif_kernel_generic(const float* __restrict__ stim,
                                   float* __restrict__ out, int N, int T) {
    int n = blockIdx.x * blockDim.x + threadIdx.x;
    if (n >= N) return;
    float v = 0.0f;
    bool p = false;
    for (int t = 0; t < T; t++) {
        lif_step(v, p, stim[(size_t)t * N + n]);
        out[(size_t)t * N + n] = v;
    }
}

extern "C" void kernel_launch(void* const* d_in, const int* in_sizes, int n_in,
                              void* d_out, int out_size) {
    const float* stim = (const float*)d_in[0];
    float* out = (float*)d_out;

    if (in_sizes[0] == T_STEPS * N_NEUR && out_size == T_STEPS * N_NEUR) {
        // 65536 pairs / 64 threads = 1024 blocks (one wave on 148 SMs)
        lif_kernel_fixed<<<N2 / 64, 64>>>((const float2*)stim, (float2*)out);
    } else {
        int T = 1000;
        int N = in_sizes[0] / T;
        int threads = 128;
        int blocks = (N + threads - 1) / threads;
        lif_kernel_generic<<<blocks, threads>>>(stim, out, N, T);
    }
}